// round 10
// baseline (speedup 1.0000x reference)
#include <cuda_runtime.h>
#include <cuda_bf16.h>
#include <math.h>

#define BATCH 2
#define DIM   256
#define NC    19
#define TOPK  256
#define HF    128
#define WF    128
#define HH    512
#define WW    512
#define SPIX  (HF*WF)            // 16384
#define NPIX  (BATCH*HH*WW)      // 524288
#define EPSV  1e-12f
#define GAMMA_MAX 0.999f
#define NB    4096               // histogram bins over w in [0,1)
#define CCAP  1024               // shared candidate capacity (threshold bin)
#define GPARTS 16                // gather blocks per class

// transpose tiling: 32 dims x 128 spatials per block
#define TR_STILES (SPIX / 128)   // 128
#define TR_DTILES (DIM / 32)     // 8
#define TR_BLOCKS (BATCH * TR_STILES * TR_DTILES)  // 2048
#define WT_BLOCKS (NPIX / 256)   // 2048 (1 pixel per thread)

// ---------------- scratch (static device memory; zero-init at load) ----------------
__device__ __align__(16) float g_fT[(size_t)BATCH*SPIX*DIM]; // features [B, HF*WF, DIM]
__device__ __align__(16) float g_cw[(size_t)NC*NPIX];        // per-class weight lists
__device__ __align__(16) int   g_cidx[(size_t)NC*NPIX];      // per-class pixel-index lists
__device__ int   g_cnt[NC];                      // per-class list counts
__device__ float g_selw[NC*TOPK];                // selected weights
__device__ int   g_seli[NC*TOPK];                // selected pixel indices
__device__ float g_wsum[NC];                     // selected weight sums
__device__ int   g_has[NC];                      // class-present flags
__device__ __align__(16) float g_part[NC*GPARTS*DIM]; // gather partials
__device__ unsigned g_done[NC];                  // gather completion tickets

// ---------------- helpers ----------------
__device__ __forceinline__ void src_coord(int o, int &i0, int &i1, float &f) {
    float s = (o + 0.5f) * 0.25f - 0.5f;
    float fl = floorf(s);
    f = s - fl;
    int i = (int)fl;
    i0 = min(max(i, 0), HF - 1);
    i1 = min(max(i + 1, 0), HF - 1);
}

__device__ __forceinline__ int w_bin(float w) {
    int b = (int)(w * (float)NB);
    return min(NB - 1, max(0, b));
}

// ================= K1: per-pixel weights + per-class list append =================
__global__ void __launch_bounds__(256) k_weights(const float* __restrict__ weight,
                                                 const int* __restrict__ labels) {
    __shared__ int s_cnt[NC];
    __shared__ int s_base[NC];
    int n = blockIdx.x * 256 + threadIdx.x;
    if (threadIdx.x < NC) s_cnt[threadIdx.x] = 0;
    __syncthreads();

    int lab = labels[n];
    bool valid = ((unsigned)lab < NC);
    float w = 0.f;
    int r = 0;
    if (valid) {
        int b   = n >> 18;
        int rem = n & (HH * WW - 1);
        int Y = rem >> 9;
        int X = rem & 511;
        int y0, y1, x0, x1; float fy, fx;
        src_coord(Y, y0, y1, fy);
        src_coord(X, x0, x1, fx);
        const float* wp = weight + ((size_t)(b * NC + lab)) * SPIX;
        float v00 = __ldg(wp + y0 * WF + x0);
        float v01 = __ldg(wp + y0 * WF + x1);
        float v10 = __ldg(wp + y1 * WF + x0);
        float v11 = __ldg(wp + y1 * WF + x1);
        w = (1.f - fy) * ((1.f - fx) * v00 + fx * v01)
          +        fy  * ((1.f - fx) * v10 + fx * v11);
        r = atomicAdd(&s_cnt[lab], 1);
    }
    __syncthreads();
    if (threadIdx.x < NC && s_cnt[threadIdx.x] > 0)
        s_base[threadIdx.x] = atomicAdd(&g_cnt[threadIdx.x], s_cnt[threadIdx.x]);
    __syncthreads();
    if (valid) {
        size_t o = (size_t)lab * NPIX + (size_t)(s_base[lab] + r);
        g_cw[o]   = w;
        g_cidx[o] = n;
    }
}

// ================= K2: select (blocks 0..18) overlapped with float4 transpose =================
__global__ void __launch_bounds__(256) k_mid(const float* __restrict__ f) {
    if (blockIdx.x >= NC) {
        // ---- NCHW -> NHWC transpose, float4 both directions (~17 KB smem) ----
        __shared__ float tile[32][132];
        int i = blockIdx.x - NC;
        int s0 = (i & (TR_STILES - 1)) * 128;
        int d0 = ((i / TR_STILES) & (TR_DTILES - 1)) * 32;
        int b  = i / (TR_STILES * TR_DTILES);
        int t  = threadIdx.x;
        int tx = t & 31;              // 32 float4 columns along s
        int ty = t >> 5;              // 8 rows
        #pragma unroll
        for (int q = 0; q < 4; q++) {
            int r = ty + q * 8;       // dim row 0..31
            float4 v = __ldg((const float4*)(f + ((size_t)(b * DIM + d0 + r)) * SPIX + s0) + tx);
            tile[r][tx * 4 + 0] = v.x;
            tile[r][tx * 4 + 1] = v.y;
            tile[r][tx * 4 + 2] = v.z;
            tile[r][tx * 4 + 3] = v.w;
        }
        __syncthreads();
        int d4 = t & 7;               // float4 group over 32 dims
        int sl = t >> 3;              // 32 spatial slots
        #pragma unroll
        for (int q = 0; q < 4; q++) {
            int s = sl + q * 32;      // local spatial 0..127
            float4 v;
            v.x = tile[d4 * 4 + 0][s];
            v.y = tile[d4 * 4 + 1][s];
            v.z = tile[d4 * 4 + 2][s];
            v.w = tile[d4 * 4 + 3][s];
            *((float4*)(g_fT + ((size_t)(b * SPIX + s0 + s)) * DIM + d0) + d4) = v;
        }
        return;
    }

    // ---- per-class exact top-256 selection (256 threads, ~21 KB smem) ----
    int c = blockIdx.x;
    int t = threadIdx.x;

    __shared__ int   hist[NB];        // 16 KB; reused as candidate store
    __shared__ float s_w[TOPK];
    __shared__ int   s_i[TOPK];
    __shared__ int   P[256];
    __shared__ float red[256];
    __shared__ int s_nsel, s_ncand, s_tb;

    int L = g_cnt[c];
    const float* cw = g_cw   + (size_t)c * NPIX;
    const int*   ci = g_cidx + (size_t)c * NPIX;

    if (t == 0) { s_nsel = 0; s_ncand = 0; s_tb = -1; }

    if (L <= TOPK) {
        __syncthreads();
        for (int i = t; i < TOPK; i += 256) {
            if (i < L) { s_w[i] = cw[i]; s_i[i] = ci[i]; }
            else       { s_w[i] = 0.f;   s_i[i] = 0; }
        }
        __syncthreads();
    } else {
        #pragma unroll
        for (int i = t; i < NB; i += 256) hist[i] = 0;
        __syncthreads();

        // pass 1: histogram (float4 vectorized)
        int L4 = L & ~3;
        for (int i = t * 4; i < L4; i += 1024) {
            float4 v = *(const float4*)(cw + i);
            atomicAdd(&hist[w_bin(v.x)], 1);
            atomicAdd(&hist[w_bin(v.y)], 1);
            atomicAdd(&hist[w_bin(v.z)], 1);
            atomicAdd(&hist[w_bin(v.w)], 1);
        }
        for (int i = L4 + t; i < L; i += 256)
            atomicAdd(&hist[w_bin(cw[i])], 1);
        __syncthreads();

        // threshold-bin discovery: 16 bins per thread, top-down
        {
            int base = NB - (t + 1) * 16;
            int s = 0;
            #pragma unroll
            for (int b = 0; b < 16; b++) s += hist[base + b];
            P[t] = s;
            __syncthreads();
            #pragma unroll
            for (int off = 1; off < 256; off <<= 1) {
                int v = (t >= off) ? P[t - off] : 0;
                __syncthreads();
                P[t] += v;
                __syncthreads();
            }
            if (P[t] >= TOPK && (t == 0 || P[t - 1] < TOPK)) {
                int acc = (t == 0) ? 0 : P[t - 1];
                for (int b = NB - t * 16 - 1; b >= base; b--) {
                    int h = hist[b];
                    if (acc + h >= TOPK) { s_tb = b; break; }
                    acc += h;
                }
            }
            __syncthreads();
        }
        int tb = s_tb;

        // pass 2: partition (hist reused as candidate store)
        float* s_cw = (float*)hist;
        int*   s_ci = hist + CCAP;
        for (int i = t * 4; i < L4; i += 1024) {
            float4 v = *(const float4*)(cw + i);
            int4   x = *(const int4*)(ci + i);
            float wq[4] = {v.x, v.y, v.z, v.w};
            int   iq[4] = {x.x, x.y, x.z, x.w};
            #pragma unroll
            for (int j = 0; j < 4; j++) {
                int bin = w_bin(wq[j]);
                if (bin > tb) {
                    int p = atomicAdd(&s_nsel, 1);
                    s_w[p] = wq[j]; s_i[p] = iq[j];
                } else if (bin == tb) {
                    int q = atomicAdd(&s_ncand, 1);
                    if (q < CCAP) { s_cw[q] = wq[j]; s_ci[q] = iq[j]; }
                }
            }
        }
        for (int i = L4 + t; i < L; i += 256) {
            float w = cw[i];
            int bin = w_bin(w);
            if (bin > tb) {
                int p = atomicAdd(&s_nsel, 1);
                s_w[p] = w; s_i[p] = ci[i];
            } else if (bin == tb) {
                int q = atomicAdd(&s_ncand, 1);
                if (q < CCAP) { s_cw[q] = w; s_ci[q] = ci[i]; }
            }
        }
        __syncthreads();

        // parallel rank select from threshold bin
        int above = s_nsel;
        int r = TOPK - above;
        int L2 = min(s_ncand, CCAP);
        if (r > 0) {
            for (int i = t; i < L2; i += 256) {
                float wi = s_cw[i];
                int rank = 0;
                for (int j = 0; j < L2; j++) {
                    float wj = s_cw[j];
                    rank += (wj > wi) || (wj == wi && j < i);
                }
                if (rank < r) { s_w[above + rank] = wi; s_i[above + rank] = s_ci[i]; }
            }
        }
        int nsel = above + ((r > 0) ? min(r, L2) : 0);
        __syncthreads();
        for (int i = t; i < TOPK; i += 256)
            if (i >= nsel) { s_w[i] = 0.f; s_i[i] = 0; }
        __syncthreads();
    }

    // weight sum + write selection to global
    red[t] = s_w[t];
    g_selw[c * TOPK + t] = s_w[t];
    g_seli[c * TOPK + t] = s_i[t];
    __syncthreads();
    if (t < 128) red[t] += red[t + 128];
    __syncthreads();
    if (t < 64) red[t] += red[t + 64];
    __syncthreads();
    if (t < 32) {
        float v = red[t] + red[t + 32];
        #pragma unroll
        for (int off = 16; off > 0; off >>= 1)
            v += __shfl_down_sync(0xFFFFFFFFu, v, off);
        if (t == 0) {
            g_wsum[c] = v;
            g_has[c]  = (L > 0) && (v > 0.f);
            g_cnt[c]  = 0;             // cleanup for next graph replay
        }
    }
}

// ================= K3: gather partials + last-block finalize =================
__global__ void __launch_bounds__(256) k_gather(
        const float* __restrict__ prototypes,
        const float* __restrict__ update_count,
        float* __restrict__ out, int out_size) {
    int c = blockIdx.x / GPARTS;       // class
    int p = blockIdx.x % GPARTS;       // part: 16 pixels
    int t = threadIdx.x;
    int d4  = t & 63;                  // float4 dim group
    int sub = t >> 6;                  // 0..3, 4 pixels each

    __shared__ float4 sv[256];
    __shared__ float red[256];
    __shared__ int s_last;

    float4 acc = make_float4(0.f, 0.f, 0.f, 0.f);
    int k0 = p * (TOPK / GPARTS) + sub * 4;
    #pragma unroll
    for (int k = k0; k < k0 + 4; k++) {
        float w = g_selw[c * TOPK + k];
        if (w > 0.f) {
            int n   = g_seli[c * TOPK + k];
            int b   = n >> 18;
            int rem = n & (HH * WW - 1);
            int Y = rem >> 9;
            int X = rem & 511;
            int y0, y1, x0, x1; float fy, fx;
            src_coord(Y, y0, y1, fy);
            src_coord(X, x0, x1, fx);
            const float4* base = (const float4*)(g_fT + ((size_t)b * SPIX) * DIM);
            float4 v00 = __ldg(base + (size_t)(y0 * WF + x0) * (DIM / 4) + d4);
            float4 v01 = __ldg(base + (size_t)(y0 * WF + x1) * (DIM / 4) + d4);
            float4 v10 = __ldg(base + (size_t)(y1 * WF + x0) * (DIM / 4) + d4);
            float4 v11 = __ldg(base + (size_t)(y1 * WF + x1) * (DIM / 4) + d4);
            float w00 = (1.f - fy) * (1.f - fx);
            float w01 = (1.f - fy) * fx;
            float w10 = fy * (1.f - fx);
            float w11 = fy * fx;
            acc.x += w * (w00 * v00.x + w01 * v01.x + w10 * v10.x + w11 * v11.x);
            acc.y += w * (w00 * v00.y + w01 * v01.y + w10 * v10.y + w11 * v11.y);
            acc.z += w * (w00 * v00.z + w01 * v01.z + w10 * v10.z + w11 * v11.z);
            acc.w += w * (w00 * v00.w + w01 * v01.w + w10 * v10.w + w11 * v11.w);
        }
    }
    sv[t] = acc;
    __syncthreads();
    if (sub < 2) {
        float4 a = sv[t], bq = sv[t + 128];
        a.x += bq.x; a.y += bq.y; a.z += bq.z; a.w += bq.w;
        sv[t] = a;
    }
    __syncthreads();
    if (sub == 0) {
        float4 a = sv[t], bq = sv[t + 64];
        a.x += bq.x; a.y += bq.y; a.z += bq.z; a.w += bq.w;
        ((float4*)g_part)[(c * GPARTS + p) * (DIM / 4) + d4] = a;
    }
    __threadfence();
    __syncthreads();
    if (t == 0)
        s_last = (atomicAdd(&g_done[c], 1u) == GPARTS - 1u);
    __syncthreads();
    if (!s_last) return;

    // finalize (only last block of this class)
    __threadfence();
    int d = t;
    float tot = 0.f;
    #pragma unroll
    for (int q = 0; q < GPARTS; q++)
        tot += g_part[(c * GPARTS + q) * DIM + d];

    float wsum = g_wsum[c];
    float proto = tot / fmaxf(wsum, EPSV);

    red[d] = proto * proto;
    __syncthreads();
    for (int s = 128; s > 0; s >>= 1) {
        if (t < s) red[t] += red[t + s];
        __syncthreads();
    }
    float nrm = sqrtf(red[0]);
    __syncthreads();
    proto = proto / fmaxf(nrm, EPSV);

    bool has = g_has[c] != 0;
    float uc = update_count[c];
    float gamma = (uc == 0.f) ? 0.f : fminf(1.f - 1.f / (uc + 1.f), GAMMA_MAX);
    float oldp = prototypes[c * DIM + d];
    float nv = has ? (gamma * oldp + (1.f - gamma) * proto) : oldp;

    red[d] = nv * nv;
    __syncthreads();
    for (int s = 128; s > 0; s >>= 1) {
        if (t < s) red[t] += red[t + s];
        __syncthreads();
    }
    float nrm2 = sqrtf(red[0]);
    out[c * DIM + d] = nv / fmaxf(nrm2, EPSV);
    if (t == 0) {
        if (out_size >= NC * DIM + NC)
            out[NC * DIM + c] = uc + (has ? 1.f : 0.f);
        g_done[c] = 0u;   // cleanup for next graph replay
    }
}

// ---------------- launch ----------------
extern "C" void kernel_launch(void* const* d_in, const int* in_sizes, int n_in,
                              void* d_out, int out_size) {
    const float* features     = (const float*)d_in[0];
    const float* weight       = (const float*)d_in[1];
    const float* prototypes   = (const float*)d_in[2];
    const float* update_count = (const float*)d_in[3];
    const int*   labels       = (const int*)d_in[4];
    float* out = (float*)d_out;

    k_weights<<<WT_BLOCKS, 256>>>(weight, labels);
    k_mid<<<NC + TR_BLOCKS, 256>>>(features);
    k_gather<<<NC * GPARTS, 256>>>(prototypes, update_count, out, out_size);
}

// round 11
// speedup vs baseline: 1.1484x; 1.1484x over previous
#include <cuda_runtime.h>
#include <cuda_bf16.h>
#include <math.h>

#define BATCH 2
#define DIM   256
#define NC    19
#define TOPK  256
#define HF    128
#define WF    128
#define HH    512
#define WW    512
#define SPIX  (HF*WF)            // 16384
#define NPIX  (BATCH*HH*WW)      // 524288
#define EPSV  1e-12f
#define GAMMA_MAX 0.999f
#define NB    4096               // histogram bins over w in [0,1)
#define CCAP  1024               // candidate capacity (threshold bin)
#define GPARTS 8                 // gather blocks per class

// transpose tiling: 32 dims x 128 spatials per block
#define TR_STILES (SPIX / 128)   // 128
#define TR_DTILES (DIM / 32)     // 8
#define TR_BLOCKS (BATCH * TR_STILES * TR_DTILES)  // 2048
#define WT_BLOCKS (NPIX / 256)   // 2048 (1 pixel per thread)

// ---------------- scratch (static device memory; zero-init at load) ----------------
__device__ __align__(16) float g_fT[(size_t)BATCH*SPIX*DIM]; // features [B, HF*WF, DIM]
__device__ __align__(16) float g_cw[(size_t)NC*NPIX];        // per-class weight lists
__device__ __align__(16) int   g_cidx[(size_t)NC*NPIX];      // per-class pixel-index lists
__device__ int   g_cnt[NC];                      // per-class list counts
__device__ float g_selw[NC*TOPK];                // selected weights
__device__ int   g_seli[NC*TOPK];                // selected pixel indices
__device__ float g_wsum[NC];                     // selected weight sums
__device__ int   g_has[NC];                      // class-present flags
__device__ int   g_ready[NC];                    // select->gather flags
__device__ __align__(16) float g_part[NC*GPARTS*DIM]; // gather partials
__device__ unsigned g_done[NC];                  // gather completion tickets

// ---------------- helpers ----------------
__device__ __forceinline__ void src_coord(int o, int &i0, int &i1, float &f) {
    float s = (o + 0.5f) * 0.25f - 0.5f;
    float fl = floorf(s);
    f = s - fl;
    int i = (int)fl;
    i0 = min(max(i, 0), HF - 1);
    i1 = min(max(i + 1, 0), HF - 1);
}

__device__ __forceinline__ int w_bin(float w) {
    int b = (int)(w * (float)NB);
    return min(NB - 1, max(0, b));
}

// ================= K1: fused float4 transpose + weights/list append =================
__global__ void __launch_bounds__(256) k_main(const float* __restrict__ f,
                                              const float* __restrict__ weight,
                                              const int* __restrict__ labels) {
    if (blockIdx.x < TR_BLOCKS) {
        // ---- NCHW -> NHWC transpose, float4 loads + STS.128 + float4 stores ----
        __shared__ __align__(16) float tile[32][132];   // row = 528 B (16B multiple)
        int i = blockIdx.x;
        int s0 = (i & (TR_STILES - 1)) * 128;
        int d0 = ((i / TR_STILES) & (TR_DTILES - 1)) * 32;
        int b  = i / (TR_STILES * TR_DTILES);
        int t  = threadIdx.x;
        int tx = t & 31;              // 32 float4 columns along s
        int ty = t >> 5;              // 8 rows
        #pragma unroll
        for (int q = 0; q < 4; q++) {
            int r = ty + q * 8;       // dim row 0..31
            float4 v = __ldg((const float4*)(f + ((size_t)(b * DIM + d0 + r)) * SPIX + s0) + tx);
            *(float4*)&tile[r][tx * 4] = v;
        }
        __syncthreads();
        int d4 = t & 7;               // float4 group over 32 dims
        int sl = t >> 3;              // 32 spatial slots
        #pragma unroll
        for (int q = 0; q < 4; q++) {
            int s = sl + q * 32;      // local spatial 0..127
            float4 v;
            v.x = tile[d4 * 4 + 0][s];
            v.y = tile[d4 * 4 + 1][s];
            v.z = tile[d4 * 4 + 2][s];
            v.w = tile[d4 * 4 + 3][s];
            *((float4*)(g_fT + ((size_t)(b * SPIX + s0 + s)) * DIM + d0) + d4) = v;
        }
    } else {
        // ---- per-pixel weight + per-class list append ----
        __shared__ int s_cnt[NC];
        __shared__ int s_base[NC];
        int n = (blockIdx.x - TR_BLOCKS) * 256 + threadIdx.x;
        if (threadIdx.x < NC) s_cnt[threadIdx.x] = 0;
        __syncthreads();

        int lab = labels[n];
        bool valid = ((unsigned)lab < NC);
        float w = 0.f;
        int r = 0;
        if (valid) {
            int b   = n >> 18;
            int rem = n & (HH * WW - 1);
            int Y = rem >> 9;
            int X = rem & 511;
            int y0, y1, x0, x1; float fy, fx;
            src_coord(Y, y0, y1, fy);
            src_coord(X, x0, x1, fx);
            const float* wp = weight + ((size_t)(b * NC + lab)) * SPIX;
            float v00 = __ldg(wp + y0 * WF + x0);
            float v01 = __ldg(wp + y0 * WF + x1);
            float v10 = __ldg(wp + y1 * WF + x0);
            float v11 = __ldg(wp + y1 * WF + x1);
            w = (1.f - fy) * ((1.f - fx) * v00 + fx * v01)
              +        fy  * ((1.f - fx) * v10 + fx * v11);
            r = atomicAdd(&s_cnt[lab], 1);
        }
        __syncthreads();
        if (threadIdx.x < NC && s_cnt[threadIdx.x] > 0)
            s_base[threadIdx.x] = atomicAdd(&g_cnt[threadIdx.x], s_cnt[threadIdx.x]);
        __syncthreads();
        if (valid) {
            size_t o = (size_t)lab * NPIX + (size_t)(s_base[lab] + r);
            g_cw[o]   = w;
            g_cidx[o] = n;
        }
    }
}

// ================= K2: select (blocks 0..18) + gather (spin-wait) in one launch =================
__global__ void __launch_bounds__(512) k_tail(
        const float* __restrict__ prototypes,
        const float* __restrict__ update_count,
        float* __restrict__ out, int out_size) {
    __shared__ __align__(16) char sbuf[22528];
    __shared__ int s_nsel, s_ncand, s_tb, s_last;
    int t = threadIdx.x;

    if (blockIdx.x < NC) {
        // ================= SELECT role (512 threads) =================
        int c = blockIdx.x;
        int*   hist = (int*)sbuf;                 // 16 KB (4096 bins)
        float* s_w  = (float*)(sbuf + 16384);     // 1 KB
        int*   s_i  = (int*)(sbuf + 17408);       // 1 KB
        int*   P    = (int*)(sbuf + 18432);       // 2 KB (512 ints)
        float* red  = (float*)(sbuf + 20480);     // 1 KB

        int L = g_cnt[c];
        const float* cw = g_cw   + (size_t)c * NPIX;
        const int*   ci = g_cidx + (size_t)c * NPIX;

        if (t == 0) { s_nsel = 0; s_ncand = 0; s_tb = -1; }

        if (L <= TOPK) {
            __syncthreads();
            for (int i = t; i < TOPK; i += 512) {
                if (i < L) { s_w[i] = cw[i]; s_i[i] = ci[i]; }
                else       { s_w[i] = 0.f;   s_i[i] = 0; }
            }
            __syncthreads();
        } else {
            #pragma unroll
            for (int i = t; i < NB; i += 512) hist[i] = 0;
            __syncthreads();

            // pass 1: histogram (float4 vectorized)
            int L4 = L & ~3;
            for (int i = t * 4; i < L4; i += 2048) {
                float4 v = *(const float4*)(cw + i);
                atomicAdd(&hist[w_bin(v.x)], 1);
                atomicAdd(&hist[w_bin(v.y)], 1);
                atomicAdd(&hist[w_bin(v.z)], 1);
                atomicAdd(&hist[w_bin(v.w)], 1);
            }
            for (int i = L4 + t; i < L; i += 512)
                atomicAdd(&hist[w_bin(cw[i])], 1);
            __syncthreads();

            // threshold-bin discovery: 8 bins per thread, top-down
            {
                int base = NB - (t + 1) * 8;
                int s = 0;
                #pragma unroll
                for (int b = 0; b < 8; b++) s += hist[base + b];
                P[t] = s;
                __syncthreads();
                #pragma unroll
                for (int off = 1; off < 512; off <<= 1) {
                    int v = (t >= off) ? P[t - off] : 0;
                    __syncthreads();
                    P[t] += v;
                    __syncthreads();
                }
                if (P[t] >= TOPK && (t == 0 || P[t - 1] < TOPK)) {
                    int acc = (t == 0) ? 0 : P[t - 1];
                    for (int b = NB - t * 8 - 1; b >= base; b--) {
                        int h = hist[b];
                        if (acc + h >= TOPK) { s_tb = b; break; }
                        acc += h;
                    }
                }
                __syncthreads();
            }
            int tb = s_tb;

            // pass 2: partition (hist reused as candidate store)
            float* s_cw = (float*)hist;
            int*   s_ci = hist + CCAP;
            for (int i = t * 4; i < L4; i += 2048) {
                float4 v = *(const float4*)(cw + i);
                int4   x = *(const int4*)(ci + i);
                float wq[4] = {v.x, v.y, v.z, v.w};
                int   iq[4] = {x.x, x.y, x.z, x.w};
                #pragma unroll
                for (int j = 0; j < 4; j++) {
                    int bin = w_bin(wq[j]);
                    if (bin > tb) {
                        int p = atomicAdd(&s_nsel, 1);
                        s_w[p] = wq[j]; s_i[p] = iq[j];
                    } else if (bin == tb) {
                        int q = atomicAdd(&s_ncand, 1);
                        if (q < CCAP) { s_cw[q] = wq[j]; s_ci[q] = iq[j]; }
                    }
                }
            }
            for (int i = L4 + t; i < L; i += 512) {
                float w = cw[i];
                int bin = w_bin(w);
                if (bin > tb) {
                    int p = atomicAdd(&s_nsel, 1);
                    s_w[p] = w; s_i[p] = ci[i];
                } else if (bin == tb) {
                    int q = atomicAdd(&s_ncand, 1);
                    if (q < CCAP) { s_cw[q] = w; s_ci[q] = ci[i]; }
                }
            }
            __syncthreads();

            // parallel rank select from threshold bin
            int above = s_nsel;
            int r = TOPK - above;
            int L2 = min(s_ncand, CCAP);
            if (r > 0) {
                for (int i = t; i < L2; i += 512) {
                    float wi = s_cw[i];
                    int rank = 0;
                    for (int j = 0; j < L2; j++) {
                        float wj = s_cw[j];
                        rank += (wj > wi) || (wj == wi && j < i);
                    }
                    if (rank < r) { s_w[above + rank] = wi; s_i[above + rank] = s_ci[i]; }
                }
            }
            int nsel = above + ((r > 0) ? min(r, L2) : 0);
            __syncthreads();
            for (int i = t; i < TOPK; i += 512)
                if (i >= nsel) { s_w[i] = 0.f; s_i[i] = 0; }
            __syncthreads();
        }

        // weight sum + publish selection
        if (t < TOPK) {
            red[t] = s_w[t];
            g_selw[c * TOPK + t] = s_w[t];
            g_seli[c * TOPK + t] = s_i[t];
        }
        __syncthreads();
        if (t < 128) red[t] += red[t + 128];
        __syncthreads();
        if (t < 64) red[t] += red[t + 64];
        __syncthreads();
        if (t < 32) {
            float v = red[t] + red[t + 32];
            #pragma unroll
            for (int off = 16; off > 0; off >>= 1)
                v += __shfl_down_sync(0xFFFFFFFFu, v, off);
            if (t == 0) {
                g_wsum[c] = v;
                g_has[c]  = (L > 0) && (v > 0.f);
                g_cnt[c]  = 0;             // cleanup for next graph replay
            }
        }
        __threadfence();                   // release: publish before flag
        __syncthreads();
        if (t == 0) atomicExch(&g_ready[c], 1);
        return;
    }

    // ================= GATHER role (512 threads) =================
    int g = blockIdx.x - NC;
    int c = g >> 3;                    // class
    int p = g & (GPARTS - 1);          // part: 32 pixels
    int d4  = t & 63;                  // float4 dim group
    int sub = t >> 6;                  // 0..7, 4 pixels each

    float4* sv  = (float4*)sbuf;       // 8 KB
    float*  red = (float*)(sbuf + 8192);

    // spin until this class's selection is published
    if (t == 0) {
        while (atomicAdd(&g_ready[c], 0) == 0) __nanosleep(64);
    }
    __syncthreads();
    __threadfence();                   // acquire

    float4 acc = make_float4(0.f, 0.f, 0.f, 0.f);
    int k0 = p * 32 + sub * 4;
    #pragma unroll
    for (int k = k0; k < k0 + 4; k++) {
        float w = g_selw[c * TOPK + k];
        if (w > 0.f) {
            int n   = g_seli[c * TOPK + k];
            int b   = n >> 18;
            int rem = n & (HH * WW - 1);
            int Y = rem >> 9;
            int X = rem & 511;
            int y0, y1, x0, x1; float fy, fx;
            src_coord(Y, y0, y1, fy);
            src_coord(X, x0, x1, fx);
            const float4* base = (const float4*)(g_fT + ((size_t)b * SPIX) * DIM);
            float4 v00 = __ldg(base + (size_t)(y0 * WF + x0) * (DIM / 4) + d4);
            float4 v01 = __ldg(base + (size_t)(y0 * WF + x1) * (DIM / 4) + d4);
            float4 v10 = __ldg(base + (size_t)(y1 * WF + x0) * (DIM / 4) + d4);
            float4 v11 = __ldg(base + (size_t)(y1 * WF + x1) * (DIM / 4) + d4);
            float w00 = (1.f - fy) * (1.f - fx);
            float w01 = (1.f - fy) * fx;
            float w10 = fy * (1.f - fx);
            float w11 = fy * fx;
            acc.x += w * (w00 * v00.x + w01 * v01.x + w10 * v10.x + w11 * v11.x);
            acc.y += w * (w00 * v00.y + w01 * v01.y + w10 * v10.y + w11 * v11.y);
            acc.z += w * (w00 * v00.z + w01 * v01.z + w10 * v10.z + w11 * v11.z);
            acc.w += w * (w00 * v00.w + w01 * v01.w + w10 * v10.w + w11 * v11.w);
        }
    }
    sv[t] = acc;
    __syncthreads();
    if (t < 256) {
        float4 a = sv[t], bq = sv[t + 256];
        a.x += bq.x; a.y += bq.y; a.z += bq.z; a.w += bq.w;
        sv[t] = a;
    }
    __syncthreads();
    if (t < 128) {
        float4 a = sv[t], bq = sv[t + 128];
        a.x += bq.x; a.y += bq.y; a.z += bq.z; a.w += bq.w;
        sv[t] = a;
    }
    __syncthreads();
    if (t < 64) {
        float4 a = sv[t], bq = sv[t + 64];
        a.x += bq.x; a.y += bq.y; a.z += bq.z; a.w += bq.w;
        ((float4*)g_part)[(c * GPARTS + p) * (DIM / 4) + t] = a;
    }
    __threadfence();
    __syncthreads();
    if (t == 0)
        s_last = (atomicAdd(&g_done[c], 1u) == GPARTS - 1u);
    __syncthreads();
    if (!s_last) return;

    // ---- finalize (only last block of this class) ----
    __threadfence();
    int d = t;
    float proto = 0.f;
    float wsum = g_wsum[c];
    if (t < DIM) {
        float tot = 0.f;
        #pragma unroll
        for (int q = 0; q < GPARTS; q++)
            tot += g_part[(c * GPARTS + q) * DIM + d];
        proto = tot / fmaxf(wsum, EPSV);
        red[d] = proto * proto;
    }
    __syncthreads();
    for (int s = 128; s > 0; s >>= 1) {
        if (t < s) red[t] += red[t + s];
        __syncthreads();
    }
    float nrm = sqrtf(red[0]);
    __syncthreads();

    bool has = g_has[c] != 0;
    float uc = update_count[c];
    float gamma = (uc == 0.f) ? 0.f : fminf(1.f - 1.f / (uc + 1.f), GAMMA_MAX);
    float nv = 0.f;
    if (t < DIM) {
        proto = proto / fmaxf(nrm, EPSV);
        float oldp = prototypes[c * DIM + d];
        nv = has ? (gamma * oldp + (1.f - gamma) * proto) : oldp;
        red[d] = nv * nv;
    }
    __syncthreads();
    for (int s = 128; s > 0; s >>= 1) {
        if (t < s) red[t] += red[t + s];
        __syncthreads();
    }
    float nrm2 = sqrtf(red[0]);
    if (t < DIM)
        out[c * DIM + d] = nv / fmaxf(nrm2, EPSV);
    if (t == 0) {
        if (out_size >= NC * DIM + NC)
            out[NC * DIM + c] = uc + (has ? 1.f : 0.f);
        g_done[c]  = 0u;   // cleanup for next graph replay
        g_ready[c] = 0;
    }
}

// ---------------- launch ----------------
extern "C" void kernel_launch(void* const* d_in, const int* in_sizes, int n_in,
                              void* d_out, int out_size) {
    const float* features     = (const float*)d_in[0];
    const float* weight       = (const float*)d_in[1];
    const float* prototypes   = (const float*)d_in[2];
    const float* update_count = (const float*)d_in[3];
    const int*   labels       = (const int*)d_in[4];
    float* out = (float*)d_out;

    k_main<<<TR_BLOCKS + WT_BLOCKS, 256>>>(features, weight, labels);
    k_tail<<<NC + NC * GPARTS, 512>>>(prototypes, update_count, out, out_size);
}

// round 12
// speedup vs baseline: 1.2223x; 1.0644x over previous
#include <cuda_runtime.h>
#include <cuda_bf16.h>
#include <math.h>

#define BATCH 2
#define DIM   256
#define NC    19
#define TOPK  256
#define HF    128
#define WF    128
#define HH    512
#define WW    512
#define SPIX  (HF*WF)            // 16384
#define NPIX  (BATCH*HH*WW)      // 524288
#define EPSV  1e-12f
#define GAMMA_MAX 0.999f
#define NB    4096               // histogram bins over w in [0,1)
#define CCAP  1024               // candidate capacity (threshold bin)
#define GPARTS 8                 // gather blocks per class

// transpose tiling: 32 dims x 128 spatials per block
#define TR_STILES (SPIX / 128)   // 128
#define TR_DTILES (DIM / 32)     // 8
#define TR_BLOCKS (BATCH * TR_STILES * TR_DTILES)  // 2048
#define WT_BLOCKS (NPIX / 256)   // 2048 (1 pixel per thread)

// ---------------- scratch (static device memory; zero-init at load) ----------------
__device__ __align__(16) float g_fT[(size_t)BATCH*SPIX*DIM]; // features [B, HF*WF, DIM]
__device__ __align__(16) float g_cw[(size_t)NC*NPIX];        // per-class weight lists
__device__ __align__(16) int   g_cidx[(size_t)NC*NPIX];      // per-class pixel-index lists
__device__ __align__(16) int   g_hist[NC*NB];                // per-class global histograms
__device__ int   g_cnt[NC];                      // per-class list counts
__device__ float g_selw[NC*TOPK];                // selected weights
__device__ int   g_seli[NC*TOPK];                // selected pixel indices
__device__ float g_wsum[NC];                     // selected weight sums
__device__ int   g_has[NC];                      // class-present flags
__device__ __align__(16) float g_part[NC*GPARTS*DIM]; // gather partials
__device__ unsigned g_done[NC];                  // gather completion tickets

// ---------------- helpers ----------------
__device__ __forceinline__ void src_coord(int o, int &i0, int &i1, float &f) {
    float s = (o + 0.5f) * 0.25f - 0.5f;
    float fl = floorf(s);
    f = s - fl;
    int i = (int)fl;
    i0 = min(max(i, 0), HF - 1);
    i1 = min(max(i + 1, 0), HF - 1);
}

__device__ __forceinline__ int w_bin(float w) {
    int b = (int)(w * (float)NB);
    return min(NB - 1, max(0, b));
}

// ================= K1: fused conflict-free transpose + weights/list/hist =================
__global__ void __launch_bounds__(256) k_main(const float* __restrict__ f,
                                              const float* __restrict__ weight,
                                              const int* __restrict__ labels) {
    if (blockIdx.x < TR_BLOCKS) {
        // ---- NCHW -> NHWC transpose; 129-word rows => conflict-free both phases ----
        __shared__ float tile[32][129];
        int i = blockIdx.x;
        int s0 = (i & (TR_STILES - 1)) * 128;
        int d0 = ((i / TR_STILES) & (TR_DTILES - 1)) * 32;
        int b  = i / (TR_STILES * TR_DTILES);
        int t  = threadIdx.x;
        int tx = t & 31;              // spatial lane
        int ty = t >> 5;              // 8 rows
        #pragma unroll
        for (int q = 0; q < 4; q++) {
            int r = ty + q * 8;       // dim row 0..31
            const float* src = f + ((size_t)(b * DIM + d0 + r)) * SPIX + s0;
            #pragma unroll
            for (int j = 0; j < 4; j++)
                tile[r][tx + 32 * j] = __ldg(src + tx + 32 * j);   // bank = r+tx: CF
        }
        __syncthreads();
        int d4 = t & 7;               // float4 group over 32 dims
        int sl = t >> 3;              // 32 spatial slots
        #pragma unroll
        for (int q = 0; q < 4; q++) {
            int s = sl + 32 * q;      // local spatial 0..127
            float4 v;                 // bank = 4d4+c+s: CF across warp
            v.x = tile[d4 * 4 + 0][s];
            v.y = tile[d4 * 4 + 1][s];
            v.z = tile[d4 * 4 + 2][s];
            v.w = tile[d4 * 4 + 3][s];
            *((float4*)(g_fT + ((size_t)(b * SPIX + s0 + s)) * DIM + d0) + d4) = v;
        }
    } else {
        // ---- per-pixel weight + per-class list append + global histogram ----
        __shared__ int s_cnt[NC];
        __shared__ int s_base[NC];
        int n = (blockIdx.x - TR_BLOCKS) * 256 + threadIdx.x;
        if (threadIdx.x < NC) s_cnt[threadIdx.x] = 0;
        __syncthreads();

        int lab = labels[n];
        bool valid = ((unsigned)lab < NC);
        float w = 0.f;
        int r = 0;
        if (valid) {
            int b   = n >> 18;
            int rem = n & (HH * WW - 1);
            int Y = rem >> 9;
            int X = rem & 511;
            int y0, y1, x0, x1; float fy, fx;
            src_coord(Y, y0, y1, fy);
            src_coord(X, x0, x1, fx);
            const float* wp = weight + ((size_t)(b * NC + lab)) * SPIX;
            float v00 = __ldg(wp + y0 * WF + x0);
            float v01 = __ldg(wp + y0 * WF + x1);
            float v10 = __ldg(wp + y1 * WF + x0);
            float v11 = __ldg(wp + y1 * WF + x1);
            w = (1.f - fy) * ((1.f - fx) * v00 + fx * v01)
              +        fy  * ((1.f - fx) * v10 + fx * v11);
            r = atomicAdd(&s_cnt[lab], 1);
            atomicAdd(&g_hist[lab * NB + w_bin(w)], 1);   // no return use -> RED
        }
        __syncthreads();
        if (threadIdx.x < NC && s_cnt[threadIdx.x] > 0)
            s_base[threadIdx.x] = atomicAdd(&g_cnt[threadIdx.x], s_cnt[threadIdx.x]);
        __syncthreads();
        if (valid) {
            size_t o = (size_t)lab * NPIX + (size_t)(s_base[lab] + r);
            g_cw[o]   = w;
            g_cidx[o] = n;
        }
    }
}

// ================= K2: per-class top-256 using precomputed histogram =================
__global__ void __launch_bounds__(1024) k_select() {
    int c = blockIdx.x;
    int t = threadIdx.x;
    int lane = t & 31, wid = t >> 5;

    __shared__ float s_w[TOPK];
    __shared__ int   s_i[TOPK];
    __shared__ float s_cw[CCAP];
    __shared__ int   s_ci[CCAP];
    __shared__ int   wsc[32];
    __shared__ float red[256];
    __shared__ int s_nsel, s_ncand, s_tb;

    int L = g_cnt[c];
    const float* cw = g_cw   + (size_t)c * NPIX;
    const int*   ci = g_cidx + (size_t)c * NPIX;

    // load my 4 histogram bins (descending chunk order) + zero for next replay
    int4* hb = (int4*)(g_hist + c * NB);
    int rid = (NB / 4 - 1) - t;              // chunk t covers bins [4rid, 4rid+3]
    int4 hv = hb[rid];
    hb[rid] = make_int4(0, 0, 0, 0);

    if (t == 0) { s_nsel = 0; s_ncand = 0; s_tb = -1; }
    __syncthreads();

    if (L <= TOPK) {
        for (int i = t; i < TOPK; i += 1024) {
            if (i < L) { s_w[i] = cw[i]; s_i[i] = ci[i]; }
            else       { s_w[i] = 0.f;   s_i[i] = 0; }
        }
        __syncthreads();
    } else {
        // ---- threshold bin from histogram (shuffle scan; bins descending) ----
        int chunk = hv.x + hv.y + hv.z + hv.w;
        int v = chunk;
        #pragma unroll
        for (int off = 1; off < 32; off <<= 1) {
            int nv = __shfl_up_sync(0xFFFFFFFFu, v, off);
            if (lane >= off) v += nv;
        }
        if (lane == 31) wsc[wid] = v;
        __syncthreads();
        if (wid == 0) {
            int ws = wsc[lane];
            int vv = ws;
            #pragma unroll
            for (int off = 1; off < 32; off <<= 1) {
                int nv = __shfl_up_sync(0xFFFFFFFFu, vv, off);
                if (lane >= off) vv += nv;
            }
            wsc[lane] = vv - ws;       // exclusive warp offset
        }
        __syncthreads();
        int P_incl = v + wsc[wid];
        int P_excl = P_incl - chunk;
        if (P_incl >= TOPK && P_excl < TOPK) {
            int acc = P_excl;
            int cnts[4] = {hv.x, hv.y, hv.z, hv.w};
            #pragma unroll
            for (int k = 3; k >= 0; k--) {
                int h = cnts[k];
                if (acc + h >= TOPK) { s_tb = 4 * rid + k; break; }
                acc += h;
            }
        }
        __syncthreads();
        int tb = s_tb;

        // ---- single list pass: partition into selected / candidates ----
        int L4 = L & ~3;
        for (int i = t * 4; i < L4; i += 4096) {
            float4 vq = *(const float4*)(cw + i);
            int4   xq = *(const int4*)(ci + i);
            float wq[4] = {vq.x, vq.y, vq.z, vq.w};
            int   iq[4] = {xq.x, xq.y, xq.z, xq.w};
            #pragma unroll
            for (int j = 0; j < 4; j++) {
                int bin = w_bin(wq[j]);
                if (bin > tb) {
                    int p = atomicAdd(&s_nsel, 1);
                    s_w[p] = wq[j]; s_i[p] = iq[j];
                } else if (bin == tb) {
                    int q = atomicAdd(&s_ncand, 1);
                    if (q < CCAP) { s_cw[q] = wq[j]; s_ci[q] = iq[j]; }
                }
            }
        }
        for (int i = L4 + t; i < L; i += 1024) {
            float w = cw[i];
            int bin = w_bin(w);
            if (bin > tb) {
                int p = atomicAdd(&s_nsel, 1);
                s_w[p] = w; s_i[p] = ci[i];
            } else if (bin == tb) {
                int q = atomicAdd(&s_ncand, 1);
                if (q < CCAP) { s_cw[q] = w; s_ci[q] = ci[i]; }
            }
        }
        __syncthreads();

        // ---- parallel rank select from threshold bin ----
        int above = s_nsel;
        int r = TOPK - above;
        int L2 = min(s_ncand, CCAP);
        if (r > 0) {
            for (int i = t; i < L2; i += 1024) {
                float wi = s_cw[i];
                int rank = 0;
                for (int j = 0; j < L2; j++) {
                    float wj = s_cw[j];
                    rank += (wj > wi) || (wj == wi && j < i);
                }
                if (rank < r) { s_w[above + rank] = wi; s_i[above + rank] = s_ci[i]; }
            }
        }
        int nsel = above + ((r > 0) ? min(r, L2) : 0);
        __syncthreads();
        for (int i = t; i < TOPK; i += 1024)
            if (i >= nsel) { s_w[i] = 0.f; s_i[i] = 0; }
        __syncthreads();
    }

    // ---- weight sum + publish selection ----
    if (t < TOPK) {
        red[t] = s_w[t];
        g_selw[c * TOPK + t] = s_w[t];
        g_seli[c * TOPK + t] = s_i[t];
    }
    __syncthreads();
    if (t < 128) red[t] += red[t + 128];
    __syncthreads();
    if (t < 64) red[t] += red[t + 64];
    __syncthreads();
    if (t < 32) {
        float v = red[t] + red[t + 32];
        #pragma unroll
        for (int off = 16; off > 0; off >>= 1)
            v += __shfl_down_sync(0xFFFFFFFFu, v, off);
        if (t == 0) {
            g_wsum[c] = v;
            g_has[c]  = (L > 0) && (v > 0.f);
            g_cnt[c]  = 0;             // cleanup for next graph replay
        }
    }
}

// ================= K3: gather partials + last-block finalize =================
__global__ void __launch_bounds__(256) k_gather(
        const float* __restrict__ prototypes,
        const float* __restrict__ update_count,
        float* __restrict__ out, int out_size) {
    int c = blockIdx.x >> 3;           // class
    int p = blockIdx.x & (GPARTS - 1); // part: 32 pixels
    int t = threadIdx.x;
    int d4  = t & 63;                  // float4 dim group
    int sub = t >> 6;                  // 0..3, 8 pixels each

    __shared__ float4 sv[256];
    __shared__ float red[256];
    __shared__ int s_last;

    float4 acc = make_float4(0.f, 0.f, 0.f, 0.f);
    int k0 = p * 32 + sub * 8;
    #pragma unroll
    for (int k = k0; k < k0 + 8; k++) {
        float w = g_selw[c * TOPK + k];
        if (w > 0.f) {
            int n   = g_seli[c * TOPK + k];
            int b   = n >> 18;
            int rem = n & (HH * WW - 1);
            int Y = rem >> 9;
            int X = rem & 511;
            int y0, y1, x0, x1; float fy, fx;
            src_coord(Y, y0, y1, fy);
            src_coord(X, x0, x1, fx);
            const float4* base = (const float4*)(g_fT + ((size_t)b * SPIX) * DIM);
            float4 v00 = __ldg(base + (size_t)(y0 * WF + x0) * (DIM / 4) + d4);
            float4 v01 = __ldg(base + (size_t)(y0 * WF + x1) * (DIM / 4) + d4);
            float4 v10 = __ldg(base + (size_t)(y1 * WF + x0) * (DIM / 4) + d4);
            float4 v11 = __ldg(base + (size_t)(y1 * WF + x1) * (DIM / 4) + d4);
            float w00 = (1.f - fy) * (1.f - fx);
            float w01 = (1.f - fy) * fx;
            float w10 = fy * (1.f - fx);
            float w11 = fy * fx;
            acc.x += w * (w00 * v00.x + w01 * v01.x + w10 * v10.x + w11 * v11.x);
            acc.y += w * (w00 * v00.y + w01 * v01.y + w10 * v10.y + w11 * v11.y);
            acc.z += w * (w00 * v00.z + w01 * v01.z + w10 * v10.z + w11 * v11.z);
            acc.w += w * (w00 * v00.w + w01 * v01.w + w10 * v10.w + w11 * v11.w);
        }
    }
    sv[t] = acc;
    __syncthreads();
    if (sub < 2) {
        float4 a = sv[t], bq = sv[t + 128];
        a.x += bq.x; a.y += bq.y; a.z += bq.z; a.w += bq.w;
        sv[t] = a;
    }
    __syncthreads();
    if (sub == 0) {
        float4 a = sv[t], bq = sv[t + 64];
        a.x += bq.x; a.y += bq.y; a.z += bq.z; a.w += bq.w;
        ((float4*)g_part)[(c * GPARTS + p) * (DIM / 4) + d4] = a;
    }
    __threadfence();
    __syncthreads();
    if (t == 0)
        s_last = (atomicAdd(&g_done[c], 1u) == GPARTS - 1u);
    __syncthreads();
    if (!s_last) return;

    // finalize (only last block of this class)
    __threadfence();
    int d = t;
    float tot = 0.f;
    #pragma unroll
    for (int q = 0; q < GPARTS; q++)
        tot += g_part[(c * GPARTS + q) * DIM + d];

    float wsum = g_wsum[c];
    float proto = tot / fmaxf(wsum, EPSV);

    red[d] = proto * proto;
    __syncthreads();
    for (int s = 128; s > 0; s >>= 1) {
        if (t < s) red[t] += red[t + s];
        __syncthreads();
    }
    float nrm = sqrtf(red[0]);
    __syncthreads();
    proto = proto / fmaxf(nrm, EPSV);

    bool has = g_has[c] != 0;
    float uc = update_count[c];
    float gamma = (uc == 0.f) ? 0.f : fminf(1.f - 1.f / (uc + 1.f), GAMMA_MAX);
    float oldp = prototypes[c * DIM + d];
    float nv = has ? (gamma * oldp + (1.f - gamma) * proto) : oldp;

    red[d] = nv * nv;
    __syncthreads();
    for (int s = 128; s > 0; s >>= 1) {
        if (t < s) red[t] += red[t + s];
        __syncthreads();
    }
    float nrm2 = sqrtf(red[0]);
    out[c * DIM + d] = nv / fmaxf(nrm2, EPSV);
    if (t == 0) {
        if (out_size >= NC * DIM + NC)
            out[NC * DIM + c] = uc + (has ? 1.f : 0.f);
        g_done[c] = 0u;   // cleanup for next graph replay
    }
}

// ---------------- launch ----------------
extern "C" void kernel_launch(void* const* d_in, const int* in_sizes, int n_in,
                              void* d_out, int out_size) {
    const float* features     = (const float*)d_in[0];
    const float* weight       = (const float*)d_in[1];
    const float* prototypes   = (const float*)d_in[2];
    const float* update_count = (const float*)d_in[3];
    const int*   labels       = (const int*)d_in[4];
    float* out = (float*)d_out;

    k_main<<<TR_BLOCKS + WT_BLOCKS, 256>>>(features, weight, labels);
    k_select<<<NC, 1024>>>();
    k_gather<<<NC * GPARTS, 256>>>(prototypes, update_count, out, out_size);
}

// round 13
// speedup vs baseline: 1.2864x; 1.0524x over previous
#include <cuda_runtime.h>
#include <cuda_bf16.h>
#include <math.h>

#define BATCH 2
#define DIM   256
#define NC    19
#define TOPK  256
#define HF    128
#define WF    128
#define HH    512
#define WW    512
#define SPIX  (HF*WF)            // 16384
#define NPIX  (BATCH*HH*WW)      // 524288
#define EPSV  1e-12f
#define GAMMA_MAX 0.999f
#define NB    4096               // histogram bins over w in [0,1)
#define CCAP  1024               // candidate capacity (threshold bin)
#define GPARTS 8                 // gather blocks per class

// transpose tiling: 32 dims x 128 spatials per block
#define TR_STILES (SPIX / 128)   // 128
#define TR_DTILES (DIM / 32)     // 8
#define TR_BLOCKS (BATCH * TR_STILES * TR_DTILES)  // 2048
#define WT_BLOCKS (NPIX / 256)   // 2048 (1 pixel per thread)

// ---------------- scratch (static device memory; zero-init at load) ----------------
__device__ __align__(16) float g_fT[(size_t)BATCH*SPIX*DIM]; // features [B, HF*WF, DIM]
__device__ __align__(16) float g_cw[(size_t)NC*NPIX];        // per-class weight lists
__device__ __align__(16) int   g_cidx[(size_t)NC*NPIX];      // per-class pixel-index lists
__device__ __align__(16) int   g_hist[NC*NB];                // per-class global histograms
__device__ int   g_cnt[NC];                      // per-class list counts
__device__ float g_selw[NC*TOPK];                // selected weights
__device__ int   g_seli[NC*TOPK];                // selected pixel indices
__device__ float g_wsum[NC];                     // selected weight sums
__device__ int   g_has[NC];                      // class-present flags
__device__ __align__(16) float g_part[NC*GPARTS*DIM]; // gather partials
__device__ unsigned g_done[NC];                  // gather completion tickets

// ---------------- helpers ----------------
__device__ __forceinline__ void src_coord(int o, int &i0, int &i1, float &f) {
    float s = (o + 0.5f) * 0.25f - 0.5f;
    float fl = floorf(s);
    f = s - fl;
    int i = (int)fl;
    i0 = min(max(i, 0), HF - 1);
    i1 = min(max(i + 1, 0), HF - 1);
}

__device__ __forceinline__ int w_bin(float w) {
    int b = (int)(w * (float)NB);
    return min(NB - 1, max(0, b));
}

// ================= K1: fused reg-transpose (XOR swizzle) + weights/list/hist =================
__global__ void __launch_bounds__(256) k_main(const float* __restrict__ f,
                                              const float* __restrict__ weight,
                                              const int* __restrict__ labels) {
    if (blockIdx.x < TR_BLOCKS) {
        // ---- NCHW -> NHWC transpose: 4x4 register micro-transpose + swizzled smem ----
        // logical tile: [128 s][32 d]; float4 slot (s, d4) stored at col4 = d4 ^ (sq&7)
        __shared__ __align__(16) float4 tile4[128 * 8];   // 16 KB
        int i = blockIdx.x;
        int s0 = (i & (TR_STILES - 1)) * 128;
        int d0 = ((i / TR_STILES) & (TR_DTILES - 1)) * 32;
        int b  = i / (TR_STILES * TR_DTILES);
        int t  = threadIdx.x;

        int dq = t >> 5;              // 0..7 : 4-dim group
        int sq = t & 31;              // 0..31: 4-spatial group
        float4 v0 = __ldg((const float4*)(f + ((size_t)(b * DIM + d0 + 4 * dq + 0)) * SPIX + s0) + sq);
        float4 v1 = __ldg((const float4*)(f + ((size_t)(b * DIM + d0 + 4 * dq + 1)) * SPIX + s0) + sq);
        float4 v2 = __ldg((const float4*)(f + ((size_t)(b * DIM + d0 + 4 * dq + 2)) * SPIX + s0) + sq);
        float4 v3 = __ldg((const float4*)(f + ((size_t)(b * DIM + d0 + 4 * dq + 3)) * SPIX + s0) + sq);
        int col4 = dq ^ (sq & 7);
        tile4[(4 * sq + 0) * 8 + col4] = make_float4(v0.x, v1.x, v2.x, v3.x);
        tile4[(4 * sq + 1) * 8 + col4] = make_float4(v0.y, v1.y, v2.y, v3.y);
        tile4[(4 * sq + 2) * 8 + col4] = make_float4(v0.z, v1.z, v2.z, v3.z);
        tile4[(4 * sq + 3) * 8 + col4] = make_float4(v0.w, v1.w, v2.w, v3.w);
        __syncthreads();

        int d4 = t & 7;               // float4 dim group
        int sl = t >> 3;              // 0..31 spatial slot
        #pragma unroll
        for (int q = 0; q < 4; q++) {
            int s = sl + 32 * q;      // local spatial 0..127
            float4 v = tile4[s * 8 + (d4 ^ ((s >> 2) & 7))];
            *((float4*)(g_fT + ((size_t)(b * SPIX + s0 + s)) * DIM + d0) + d4) = v;
        }
    } else {
        // ---- per-pixel weight + per-class list append + global histogram ----
        __shared__ int s_cnt[NC];
        __shared__ int s_base[NC];
        int n = (blockIdx.x - TR_BLOCKS) * 256 + threadIdx.x;
        if (threadIdx.x < NC) s_cnt[threadIdx.x] = 0;
        __syncthreads();

        int lab = labels[n];
        bool valid = ((unsigned)lab < NC);
        float w = 0.f;
        int r = 0;
        if (valid) {
            int b   = n >> 18;
            int rem = n & (HH * WW - 1);
            int Y = rem >> 9;
            int X = rem & 511;
            int y0, y1, x0, x1; float fy, fx;
            src_coord(Y, y0, y1, fy);
            src_coord(X, x0, x1, fx);
            const float* wp = weight + ((size_t)(b * NC + lab)) * SPIX;
            float v00 = __ldg(wp + y0 * WF + x0);
            float v01 = __ldg(wp + y0 * WF + x1);
            float v10 = __ldg(wp + y1 * WF + x0);
            float v11 = __ldg(wp + y1 * WF + x1);
            w = (1.f - fy) * ((1.f - fx) * v00 + fx * v01)
              +        fy  * ((1.f - fx) * v10 + fx * v11);
            r = atomicAdd(&s_cnt[lab], 1);
            atomicAdd(&g_hist[lab * NB + w_bin(w)], 1);   // no return use -> RED
        }
        __syncthreads();
        if (threadIdx.x < NC && s_cnt[threadIdx.x] > 0)
            s_base[threadIdx.x] = atomicAdd(&g_cnt[threadIdx.x], s_cnt[threadIdx.x]);
        __syncthreads();
        if (valid) {
            size_t o = (size_t)lab * NPIX + (size_t)(s_base[lab] + r);
            g_cw[o]   = w;
            g_cidx[o] = n;
        }
    }
}

// ================= K2: per-class top-256 using precomputed histogram =================
__global__ void __launch_bounds__(1024) k_select() {
    int c = blockIdx.x;
    int t = threadIdx.x;
    int lane = t & 31, wid = t >> 5;

    __shared__ float s_w[TOPK];
    __shared__ int   s_i[TOPK];
    __shared__ float s_cw[CCAP];
    __shared__ int   s_ci[CCAP];
    __shared__ int   wsc[32];
    __shared__ float red[256];
    __shared__ int s_nsel, s_ncand, s_tb;

    int L = g_cnt[c];
    const float* cw = g_cw   + (size_t)c * NPIX;
    const int*   ci = g_cidx + (size_t)c * NPIX;

    // load my 4 histogram bins (descending chunk order) + zero for next replay
    int4* hb = (int4*)(g_hist + c * NB);
    int rid = (NB / 4 - 1) - t;              // chunk t covers bins [4rid, 4rid+3]
    int4 hv = hb[rid];
    hb[rid] = make_int4(0, 0, 0, 0);

    if (t == 0) { s_nsel = 0; s_ncand = 0; s_tb = -1; }
    __syncthreads();

    if (L <= TOPK) {
        for (int i = t; i < TOPK; i += 1024) {
            if (i < L) { s_w[i] = cw[i]; s_i[i] = ci[i]; }
            else       { s_w[i] = 0.f;   s_i[i] = 0; }
        }
        __syncthreads();
    } else {
        // ---- threshold bin from histogram (shuffle scan; bins descending) ----
        int chunk = hv.x + hv.y + hv.z + hv.w;
        int v = chunk;
        #pragma unroll
        for (int off = 1; off < 32; off <<= 1) {
            int nv = __shfl_up_sync(0xFFFFFFFFu, v, off);
            if (lane >= off) v += nv;
        }
        if (lane == 31) wsc[wid] = v;
        __syncthreads();
        if (wid == 0) {
            int ws = wsc[lane];
            int vv = ws;
            #pragma unroll
            for (int off = 1; off < 32; off <<= 1) {
                int nv = __shfl_up_sync(0xFFFFFFFFu, vv, off);
                if (lane >= off) vv += nv;
            }
            wsc[lane] = vv - ws;       // exclusive warp offset
        }
        __syncthreads();
        int P_incl = v + wsc[wid];
        int P_excl = P_incl - chunk;
        if (P_incl >= TOPK && P_excl < TOPK) {
            int acc = P_excl;
            int cnts[4] = {hv.x, hv.y, hv.z, hv.w};
            #pragma unroll
            for (int k = 3; k >= 0; k--) {
                int h = cnts[k];
                if (acc + h >= TOPK) { s_tb = 4 * rid + k; break; }
                acc += h;
            }
        }
        __syncthreads();
        int tb = s_tb;

        // ---- single list pass: partition into selected / candidates ----
        int L4 = L & ~3;
        for (int i = t * 4; i < L4; i += 4096) {
            float4 vq = *(const float4*)(cw + i);
            int4   xq = *(const int4*)(ci + i);
            float wq[4] = {vq.x, vq.y, vq.z, vq.w};
            int   iq[4] = {xq.x, xq.y, xq.z, xq.w};
            #pragma unroll
            for (int j = 0; j < 4; j++) {
                int bin = w_bin(wq[j]);
                if (bin > tb) {
                    int p = atomicAdd(&s_nsel, 1);
                    s_w[p] = wq[j]; s_i[p] = iq[j];
                } else if (bin == tb) {
                    int q = atomicAdd(&s_ncand, 1);
                    if (q < CCAP) { s_cw[q] = wq[j]; s_ci[q] = iq[j]; }
                }
            }
        }
        for (int i = L4 + t; i < L; i += 1024) {
            float w = cw[i];
            int bin = w_bin(w);
            if (bin > tb) {
                int p = atomicAdd(&s_nsel, 1);
                s_w[p] = w; s_i[p] = ci[i];
            } else if (bin == tb) {
                int q = atomicAdd(&s_ncand, 1);
                if (q < CCAP) { s_cw[q] = w; s_ci[q] = ci[i]; }
            }
        }
        __syncthreads();

        // ---- parallel rank select from threshold bin ----
        int above = s_nsel;
        int r = TOPK - above;
        int L2 = min(s_ncand, CCAP);
        if (r > 0) {
            for (int i = t; i < L2; i += 1024) {
                float wi = s_cw[i];
                int rank = 0;
                for (int j = 0; j < L2; j++) {
                    float wj = s_cw[j];
                    rank += (wj > wi) || (wj == wi && j < i);
                }
                if (rank < r) { s_w[above + rank] = wi; s_i[above + rank] = s_ci[i]; }
            }
        }
        int nsel = above + ((r > 0) ? min(r, L2) : 0);
        __syncthreads();
        for (int i = t; i < TOPK; i += 1024)
            if (i >= nsel) { s_w[i] = 0.f; s_i[i] = 0; }
        __syncthreads();
    }

    // ---- weight sum + publish selection ----
    if (t < TOPK) {
        red[t] = s_w[t];
        g_selw[c * TOPK + t] = s_w[t];
        g_seli[c * TOPK + t] = s_i[t];
    }
    __syncthreads();
    if (t < 128) red[t] += red[t + 128];
    __syncthreads();
    if (t < 64) red[t] += red[t + 64];
    __syncthreads();
    if (t < 32) {
        float v = red[t] + red[t + 32];
        #pragma unroll
        for (int off = 16; off > 0; off >>= 1)
            v += __shfl_down_sync(0xFFFFFFFFu, v, off);
        if (t == 0) {
            g_wsum[c] = v;
            g_has[c]  = (L > 0) && (v > 0.f);
            g_cnt[c]  = 0;             // cleanup for next graph replay
        }
    }
}

// ================= K3: gather partials + last-block finalize =================
__global__ void __launch_bounds__(256) k_gather(
        const float* __restrict__ prototypes,
        const float* __restrict__ update_count,
        float* __restrict__ out, int out_size) {
    int c = blockIdx.x >> 3;           // class
    int p = blockIdx.x & (GPARTS - 1); // part: 32 pixels
    int t = threadIdx.x;
    int d4  = t & 63;                  // float4 dim group
    int sub = t >> 6;                  // 0..3, 8 pixels each

    __shared__ float4 sv[256];
    __shared__ float red[256];
    __shared__ int s_last;

    float4 acc = make_float4(0.f, 0.f, 0.f, 0.f);
    int k0 = p * 32 + sub * 8;
    #pragma unroll
    for (int k = k0; k < k0 + 8; k++) {
        float w = g_selw[c * TOPK + k];
        if (w > 0.f) {
            int n   = g_seli[c * TOPK + k];
            int b   = n >> 18;
            int rem = n & (HH * WW - 1);
            int Y = rem >> 9;
            int X = rem & 511;
            int y0, y1, x0, x1; float fy, fx;
            src_coord(Y, y0, y1, fy);
            src_coord(X, x0, x1, fx);
            const float4* base = (const float4*)(g_fT + ((size_t)b * SPIX) * DIM);
            float4 v00 = __ldg(base + (size_t)(y0 * WF + x0) * (DIM / 4) + d4);
            float4 v01 = __ldg(base + (size_t)(y0 * WF + x1) * (DIM / 4) + d4);
            float4 v10 = __ldg(base + (size_t)(y1 * WF + x0) * (DIM / 4) + d4);
            float4 v11 = __ldg(base + (size_t)(y1 * WF + x1) * (DIM / 4) + d4);
            float w00 = (1.f - fy) * (1.f - fx);
            float w01 = (1.f - fy) * fx;
            float w10 = fy * (1.f - fx);
            float w11 = fy * fx;
            acc.x += w * (w00 * v00.x + w01 * v01.x + w10 * v10.x + w11 * v11.x);
            acc.y += w * (w00 * v00.y + w01 * v01.y + w10 * v10.y + w11 * v11.y);
            acc.z += w * (w00 * v00.z + w01 * v01.z + w10 * v10.z + w11 * v11.z);
            acc.w += w * (w00 * v00.w + w01 * v01.w + w10 * v10.w + w11 * v11.w);
        }
    }
    sv[t] = acc;
    __syncthreads();
    if (sub < 2) {
        float4 a = sv[t], bq = sv[t + 128];
        a.x += bq.x; a.y += bq.y; a.z += bq.z; a.w += bq.w;
        sv[t] = a;
    }
    __syncthreads();
    if (sub == 0) {
        float4 a = sv[t], bq = sv[t + 64];
        a.x += bq.x; a.y += bq.y; a.z += bq.z; a.w += bq.w;
        ((float4*)g_part)[(c * GPARTS + p) * (DIM / 4) + d4] = a;
    }
    __threadfence();
    __syncthreads();
    if (t == 0)
        s_last = (atomicAdd(&g_done[c], 1u) == GPARTS - 1u);
    __syncthreads();
    if (!s_last) return;

    // finalize (only last block of this class)
    __threadfence();
    int d = t;
    float tot = 0.f;
    #pragma unroll
    for (int q = 0; q < GPARTS; q++)
        tot += g_part[(c * GPARTS + q) * DIM + d];

    float wsum = g_wsum[c];
    float proto = tot / fmaxf(wsum, EPSV);

    red[d] = proto * proto;
    __syncthreads();
    for (int s = 128; s > 0; s >>= 1) {
        if (t < s) red[t] += red[t + s];
        __syncthreads();
    }
    float nrm = sqrtf(red[0]);
    __syncthreads();
    proto = proto / fmaxf(nrm, EPSV);

    bool has = g_has[c] != 0;
    float uc = update_count[c];
    float gamma = (uc == 0.f) ? 0.f : fminf(1.f - 1.f / (uc + 1.f), GAMMA_MAX);
    float oldp = prototypes[c * DIM + d];
    float nv = has ? (gamma * oldp + (1.f - gamma) * proto) : oldp;

    red[d] = nv * nv;
    __syncthreads();
    for (int s = 128; s > 0; s >>= 1) {
        if (t < s) red[t] += red[t + s];
        __syncthreads();
    }
    float nrm2 = sqrtf(red[0]);
    out[c * DIM + d] = nv / fmaxf(nrm2, EPSV);
    if (t == 0) {
        if (out_size >= NC * DIM + NC)
            out[NC * DIM + c] = uc + (has ? 1.f : 0.f);
        g_done[c] = 0u;   // cleanup for next graph replay
    }
}

// ---------------- launch ----------------
extern "C" void kernel_launch(void* const* d_in, const int* in_sizes, int n_in,
                              void* d_out, int out_size) {
    const float* features     = (const float*)d_in[0];
    const float* weight       = (const float*)d_in[1];
    const float* prototypes   = (const float*)d_in[2];
    const float* update_count = (const float*)d_in[3];
    const int*   labels       = (const int*)d_in[4];
    float* out = (float*)d_out;

    k_main<<<TR_BLOCKS + WT_BLOCKS, 256>>>(features, weight, labels);
    k_select<<<NC, 1024>>>();
    k_gather<<<NC * GPARTS, 256>>>(prototypes, update_count, out, out_size);
}